// round 11
// baseline (speedup 1.0000x reference)
#include <cuda_runtime.h>
#include <math.h>

// Problem constants
#define NSEQ   128          // 2*BATCH sequences
#define TLEN   64           // frames per sequence
#define DIMS   13           // feature dim
#define NPAIRS 8128         // NSEQ*(NSEQ-1)/2, pairs with a<b (diag is masked to 0)
#define WPB    4            // warps per block (pairs kernel)

typedef unsigned long long u64;

// Asymmetric padding with A pre-scaled by -2 so that
//   dot16(A'_row, B_col) = -2*dot13 + |a|^2 + |b|^2 = D  (exactly)
//   A-copy: slots [0..12]=-2x, [13]=-2|x|^2, [14]=1,     [15]=0
//   B-copy: slots [0..12]=x,   [13]=-0.5,    [14]=|x|^2, [15]=0
// 16B alignment is REQUIRED: these are read via 16-byte vector loads.
static __device__ __align__(16) float g_xpadA[NSEQ * TLEN * 16];
static __device__ __align__(16) float g_xpadB[NSEQ * TLEN * 16];
static __device__ float g_R[NSEQ * NSEQ];          // raw soft-DTW values (diag never touched)
static __device__ float g_partial[NSEQ];           // per-row (lse - pos) terms

__device__ __forceinline__ float ex2f(float x) {
    float r; asm("ex2.approx.ftz.f32 %0, %1;" : "=f"(r) : "f"(x)); return r;
}
__device__ __forceinline__ float lg2f(float x) {
    float r; asm("lg2.approx.ftz.f32 %0, %1;" : "=f"(r) : "f"(x)); return r;
}
__device__ __forceinline__ u64 fmul2(u64 a, u64 b) {
    u64 d; asm("mul.rn.f32x2 %0, %1, %2;" : "=l"(d) : "l"(a), "l"(b)); return d;
}
__device__ __forceinline__ u64 ffma2(u64 a, u64 b, u64 c) {
    u64 d; asm("fma.rn.f32x2 %0, %1, %2, %3;" : "=l"(d) : "l"(a), "l"(b), "l"(c)); return d;
}
__device__ __forceinline__ float pairsum(u64 v) {
    float lo, hi;
    asm("mov.b64 {%0, %1}, %2;" : "=f"(lo), "=f"(hi) : "l"(v));
    return lo + hi;
}

// ---------------------------------------------------------------------------
// Kernel 1: build both padded copies.
// ---------------------------------------------------------------------------
__global__ void prep_kernel(const float* __restrict__ xxx, const float* __restrict__ yyy) {
    int f = blockIdx.x * blockDim.x + threadIdx.x;
    if (f >= NSEQ * TLEN) return;
    int n = f >> 6;          // sequence
    int t = f & 63;          // frame
    const float* src = (n < 64) ? (xxx + (size_t)(n * TLEN + t) * DIMS)
                                : (yyy + (size_t)((n - 64) * TLEN + t) * DIMS);
    float* dstA = &g_xpadA[(size_t)f * 16];
    float* dstB = &g_xpadB[(size_t)f * 16];
    float s = 0.f;
#pragma unroll
    for (int d = 0; d < DIMS; ++d) {
        float v = src[d];
        s = fmaf(v, v, s);
        dstA[d] = -2.0f * v;
        dstB[d] = v;
    }
    dstA[13] = -2.0f * s; dstB[13] = -0.5f;
    dstA[14] = 1.0f;      dstB[14] = s;
    dstA[15] = 0.f;       dstB[15] = 0.f;
}

// ---------------------------------------------------------------------------
// Kernel 2: one warp per (a<b) pair. Fused distance computation + soft-DTW.
//
// Lane L owns row (S*32 + L) of the 64x64 DP table; wavefront sweep: at step
// k lane L handles cell (row, j = k-L).
//
//  * D[row][k] produced one column per step (xb[k] broadcast from smem, xa
//    row-resident in packed f32x2 registers; norms AND the -2 factor folded
//    into the padding so D = pairsum(dot16) directly) into a 32-deep smem
//    ring. The ring is a PER-LANE delay line: lane L writes bank L and reads
//    bank L, L steps later (same thread, program order, no syncs, no
//    conflicts). Lane 0's delay is 0 steps; to avoid a same-step STS->LDS
//    same-address hazard (B300 smem has no store forwarding) lane 0 reads a
//    one-back slot and takes dnew from register via SEL.
//  * DP neighbors: up = shfl_up(r1); diag = previous step's (post-override)
//    up carried in a register (identity diag_k == up_{k-1}) -> ONE shfl/step.
//  * Two 32-row strips, each a separately-instantiated template (S folded to
//    a constant so all strip predicates vanish); boundary row via s_rowbuf.
//  * softmin with 3 MUFU ops: the min argument contributes ex2(0)=1; with
//    m1=min(u,l), M1=max(u,l), mm=min(m1,dg), xx=max(m1,dg), the two
//    non-min values are exactly {xx, M1}.
//  * Phase B has NO lane-0 up override: lane 0's cells there are all invalid
//    (rnew forced to INFV by the SEL) and its up/dg feed only its own
//    discarded results; lane 1 reads lane 0's r1 via shfl, which is correct
//    (R[0][63] at entry, INFV after).
//  * Strip fusion / cross-pair overlap were analyzed and rejected: both
//    conserve total issue slots and MUFU count, and this kernel is
//    issue/MUFU-co-bound at 20 warps/SM, so steps-per-warp is not the
//    binding quantity.
// ---------------------------------------------------------------------------

#define SOFTMIN_CELL(up, left, diag, dcur, validExpr, rnew)                    \
    {                                                                          \
        const float m1_ = fminf(up, left);                                     \
        const float M1_ = fmaxf(up, left);                                     \
        const float mm_ = fminf(m1_, diag);                                    \
        const float xx_ = fmaxf(m1_, diag);                                    \
        const float mk_ = mm_ * KK;                                            \
        const float e1_ = ex2f(fmaf(-KK, xx_, mk_));                           \
        const float e2_ = ex2f(fmaf(-KK, M1_, mk_));                           \
        const float sm_ = fmaf(-GL2, lg2f(1.0f + e1_ + e2_), mm_);             \
        rnew = (validExpr) ? (dcur + sm_) : INFV;                              \
    }

// D = dot16(A'_row, xb[k]) via 8 packed f32x2 FMAs + horizontal add
#define PROD_D(bp, Aa, Ab, Ac, Ad, dOut)                                       \
    {                                                                          \
        const ulonglong2 Ba_ = (bp)[0];                                        \
        const ulonglong2 Bb_ = (bp)[1];                                        \
        const ulonglong2 Bc_ = (bp)[2];                                        \
        const ulonglong2 Bd_ = (bp)[3];                                        \
        u64 acc_ = fmul2(Aa.x, Ba_.x);                                         \
        acc_ = ffma2(Aa.y, Ba_.y, acc_);                                       \
        acc_ = ffma2(Ab.x, Bb_.x, acc_);                                       \
        acc_ = ffma2(Ab.y, Bb_.y, acc_);                                       \
        acc_ = ffma2(Ac.x, Bc_.x, acc_);                                       \
        acc_ = ffma2(Ac.y, Bc_.y, acc_);                                       \
        acc_ = ffma2(Ad.x, Bd_.x, acc_);                                       \
        acc_ = ffma2(Ad.y, Bd_.y, acc_);                                       \
        dOut = pairsum(acc_);                                                  \
    }

// One 32-row strip of the DP. S is a compile-time constant (0 or 1) so every
// strip-dependent predicate folds away. Returns lane's final r1
// (lane 31, strip 1 => R[63][63]).
template <int S>
__device__ __forceinline__ float dp_strip(
    int L, int Lq, int a,
    const float* __restrict__ s_xb,   // this warp's xb tile (B-padded)
    float* __restrict__ s_ring,       // this warp's 32x32 D ring
    float* __restrict__ s_rowbuf)     // this warp's boundary row
{
    const float INFV = 1e10f;
    const float KK   = 14.4269504088896341f;   // log2(e)/gamma, gamma = 0.1
    const float GL2  = 0.069314718055994531f;  // gamma * ln(2)

    const int row = S * 32 + L;
    const ulonglong2* ap = (const ulonglong2*)&g_xpadA[((size_t)a * TLEN + row) * 16];
    const ulonglong2 Aa = ap[0], Ab = ap[1], Ac = ap[2], Ad = ap[3];

    float r1 = INFV;
    // diag carry: holds previous step's (post-override) up. First use at k=0
    // is cell (row, -L): only lane 0 / strip 0 needs corner R(-1,-1)=0 there
    // (feeding cell (0,0)); everything else wants INFV.
    float dg = (S == 0 && L == 0) ? 0.0f : INFV;

    // ---------------- Phase A: k = 0..63 (produce D column + consume) -------
#pragma unroll 2
    for (int k = 0; k < TLEN; ++k) {
        // produce D[row][k]
        float dnew;
        {
            const ulonglong2* bp = (const ulonglong2*)&s_xb[k * 16];
            PROD_D(bp, Aa, Ab, Ac, Ad, dnew);
            s_ring[(k & 31) * 32 + L] = dnew;   // bank = L, conflict-free
        }

        // consume cell (row, j = k-L). Lane 0 reads a one-back slot (Lq=1)
        // and takes dnew from register: no same-step same-address LDS.
        const float dld = s_ring[((k - Lq) & 31) * 32 + L];
        const float dcur = (L == 0) ? dnew : dld;
        float up = __shfl_up_sync(0xffffffffu, r1, 1);
        if (L == 0) up = (S == 0) ? INFV : s_rowbuf[k];   // R[31][j], j==k
        const float left = r1;

        float rnew;
        SOFTMIN_CELL(up, left, dg, dcur, k >= L, rnew);
        if (S == 0 && L == 31 && k >= L) s_rowbuf[k - L] = rnew;
        dg = up;       // diag for next step
        r1 = rnew;
    }

    // ---------------- Phase B: k = 64..94 (drain; j = k-L in [33,63]) -------
    // Lane 0 is invalid throughout phase B; no up override needed (see header
    // comment). Its off-by-one ring read is likewise discarded by the SEL.
#pragma unroll 2
    for (int k = TLEN; k < TLEN + 31; ++k) {
        const float dcur = s_ring[((k - Lq) & 31) * 32 + L];
        const float up = __shfl_up_sync(0xffffffffu, r1, 1);
        const float left = r1;

        float rnew;
        SOFTMIN_CELL(up, left, dg, dcur, k < L + TLEN, rnew);
        if (S == 0 && L == 31) s_rowbuf[k - 31] = rnew;   // j in [33,63]
        dg = up;
        r1 = rnew;
    }
    return r1;
}

__global__ void __launch_bounds__(WPB * 32, 5) pairs_kernel() {
    __shared__ __align__(16) float s_xb[WPB][TLEN * 16];  // 16 KB: xb frames (B-padded)
    __shared__ float s_ring[WPB][32 * 32];                // 16 KB: D-column ring
    __shared__ float s_rowbuf[WPB][TLEN];                 //  1 KB: strip boundary row

    const int w = threadIdx.x >> 5;
    const int L = threadIdx.x & 31;
    const int Lq = L + (L == 0);    // ring read delay (lane 0 biased one back)
    const int idx = blockIdx.x * WPB + w;
    if (idx >= NPAIRS) return;

    // --- decode triangular pair index: off(a) = a*(255-a)/2 ---
    int a = (int)((255.0f - sqrtf(fmaxf(0.f, 65025.0f - 8.0f * (float)idx))) * 0.5f);
    if (a < 0) a = 0;
    if (a > 126) a = 126;
    while (a > 0 && (a * (255 - a)) / 2 > idx) --a;
    while (((a + 1) * (254 - a)) / 2 <= idx) ++a;
    const int b = a + 1 + (idx - (a * (255 - a)) / 2);

    // --- stage xb (64 frames x 16 floats, B padding) into shared ---
    {
        const float4* src4 = (const float4*)&g_xpadB[(size_t)b * TLEN * 16];
        float4* dst4 = (float4*)&s_xb[w][0];
#pragma unroll
        for (int t = L; t < TLEN * 4; t += 32) dst4[t] = src4[t];
    }
    __syncwarp();

    dp_strip<0>(L, Lq, a, s_xb[w], s_ring[w], s_rowbuf[w]);
    __syncwarp();   // strip 0's rowbuf writes -> strip 1's lane-0 reads
    const float Rv = dp_strip<1>(L, Lq, a, s_xb[w], s_ring[w], s_rowbuf[w]);

    if (L == 31) {
        g_R[a * NSEQ + b] = Rv;         // R[63][63]
        g_R[b * NSEQ + a] = Rv;         // sim is symmetric
    }
}

// ---------------------------------------------------------------------------
// Kernel 3a: per-row contrastive term. ONE warp per block, 128 blocks -> rows
// spread across ~128 SMs (better chip-wide MLP than 32x4). Warp r owns row r.
// sim = R/ENERGY with zero diagonal; g_partial[r] = lse_r - pos_r.
// Deterministic: fixed butterfly reduction order.
// ---------------------------------------------------------------------------
__global__ void rowreduce_kernel() {
    const int r    = blockIdx.x;              // row 0..127
    const int lane = threadIdx.x;             // 32 threads
    const float INV_E = 2.0f;                 // 1/ENERGY
    const float L2E   = 1.4426950408889634f;  // log2(e)
    const float LN2   = 0.6931471805599453f;

    // Each lane holds 4 columns: c = q*32 + lane
    float v[4];
#pragma unroll
    for (int q = 0; q < 4; ++q) {
        const int c = q * 32 + lane;
        v[q] = (c == r) ? 0.0f : g_R[r * NSEQ + c] * INV_E;
    }

    // Row max (diagonal contributes 0, already included via v)
    float mx = fmaxf(fmaxf(v[0], v[1]), fmaxf(v[2], v[3]));
#pragma unroll
    for (int o = 16; o > 0; o >>= 1)
        mx = fmaxf(mx, __shfl_xor_sync(0xffffffffu, mx, o));

    // Sum of exp(v - mx)
    float sum = 0.f;
#pragma unroll
    for (int q = 0; q < 4; ++q)
        sum += ex2f((v[q] - mx) * L2E);
#pragma unroll
    for (int o = 16; o > 0; o >>= 1)
        sum += __shfl_xor_sync(0xffffffffu, sum, o);

    if (lane == 0) {
        const float lse = fmaf(LN2, lg2f(sum), mx);
        const float pos = g_R[r * NSEQ + ((r + 64) & 127)] * INV_E;
        g_partial[r] = lse - pos;
    }
}

// ---------------------------------------------------------------------------
// Kernel 3b: final mean over the 128 per-row terms (one warp, fixed order).
// ---------------------------------------------------------------------------
__global__ void finalsum_kernel(float* __restrict__ out) {
    const int lane = threadIdx.x;   // 32 threads
    float s = g_partial[lane] + g_partial[lane + 32]
            + g_partial[lane + 64] + g_partial[lane + 96];
#pragma unroll
    for (int o = 16; o > 0; o >>= 1)
        s += __shfl_xor_sync(0xffffffffu, s, o);
    if (lane == 0) out[0] = s * (1.0f / 128.0f);
}

// ---------------------------------------------------------------------------
extern "C" void kernel_launch(void* const* d_in, const int* in_sizes, int n_in,
                              void* d_out, int out_size) {
    const float* xxx = (const float*)d_in[0];
    const float* yyy = (const float*)d_in[1];
    float* out = (float*)d_out;

    prep_kernel<<<(NSEQ * TLEN + 255) / 256, 256>>>(xxx, yyy);
    pairs_kernel<<<NPAIRS / WPB, WPB * 32>>>();
    rowreduce_kernel<<<NSEQ, 32>>>();
    finalsum_kernel<<<1, 32>>>(out);
}

// round 15
// speedup vs baseline: 1.0300x; 1.0300x over previous
#include <cuda_runtime.h>
#include <math.h>

// Problem constants
#define NSEQ   128          // 2*BATCH sequences
#define TLEN   64           // frames per sequence
#define DIMS   13           // feature dim
#define NPAIRS 8128         // NSEQ*(NSEQ-1)/2, pairs with a<b (diag is masked to 0)
#define WPB    2            // warps per block (pairs kernel) — occupancy probe 4->2

typedef unsigned long long u64;

// Asymmetric padding with A pre-scaled by -2 so that
//   dot16(A'_row, B_col) = -2*dot13 + |a|^2 + |b|^2 = D  (exactly)
//   A-copy: slots [0..12]=-2x, [13]=-2|x|^2, [14]=1,     [15]=0
//   B-copy: slots [0..12]=x,   [13]=-0.5,    [14]=|x|^2, [15]=0
// 16B alignment is REQUIRED: these are read via 16-byte vector loads.
static __device__ __align__(16) float g_xpadA[NSEQ * TLEN * 16];
static __device__ __align__(16) float g_xpadB[NSEQ * TLEN * 16];
static __device__ float g_R[NSEQ * NSEQ];          // raw soft-DTW values (diag never touched)

__device__ __forceinline__ float ex2f(float x) {
    float r; asm("ex2.approx.ftz.f32 %0, %1;" : "=f"(r) : "f"(x)); return r;
}
__device__ __forceinline__ float lg2f(float x) {
    float r; asm("lg2.approx.ftz.f32 %0, %1;" : "=f"(r) : "f"(x)); return r;
}
__device__ __forceinline__ u64 fmul2(u64 a, u64 b) {
    u64 d; asm("mul.rn.f32x2 %0, %1, %2;" : "=l"(d) : "l"(a), "l"(b)); return d;
}
__device__ __forceinline__ u64 ffma2(u64 a, u64 b, u64 c) {
    u64 d; asm("fma.rn.f32x2 %0, %1, %2, %3;" : "=l"(d) : "l"(a), "l"(b), "l"(c)); return d;
}
__device__ __forceinline__ float pairsum(u64 v) {
    float lo, hi;
    asm("mov.b64 {%0, %1}, %2;" : "=f"(lo), "=f"(hi) : "l"(v));
    return lo + hi;
}

// ---------------------------------------------------------------------------
// Kernel 1: build both padded copies.
// ---------------------------------------------------------------------------
__global__ void prep_kernel(const float* __restrict__ xxx, const float* __restrict__ yyy) {
    int f = blockIdx.x * blockDim.x + threadIdx.x;
    if (f >= NSEQ * TLEN) return;
    int n = f >> 6;          // sequence
    int t = f & 63;          // frame
    const float* src = (n < 64) ? (xxx + (size_t)(n * TLEN + t) * DIMS)
                                : (yyy + (size_t)((n - 64) * TLEN + t) * DIMS);
    float* dstA = &g_xpadA[(size_t)f * 16];
    float* dstB = &g_xpadB[(size_t)f * 16];
    float s = 0.f;
#pragma unroll
    for (int d = 0; d < DIMS; ++d) {
        float v = src[d];
        s = fmaf(v, v, s);
        dstA[d] = -2.0f * v;
        dstB[d] = v;
    }
    dstA[13] = -2.0f * s; dstB[13] = -0.5f;
    dstA[14] = 1.0f;      dstB[14] = s;
    dstA[15] = 0.f;       dstB[15] = 0.f;
}

// ---------------------------------------------------------------------------
// Kernel 2: one warp per (a<b) pair. Fused distance computation + soft-DTW.
// Lane L owns row (S*32+L); wavefront: at step k lane L does cell (row, k-L).
// D column produced per step into a 32-deep per-lane smem delay ring; DP
// neighbors via ONE shfl + register diag carry; 3-MUFU softmin; templated
// strips with smem rowbuf at the boundary. Unroll 4: lets ptxas strength-
// reduce ring/xb addresses to immediate offsets (addressing IMADs were ~40%
// of the issue budget per the R11 back-computation).
// ---------------------------------------------------------------------------

#define SOFTMIN_CELL(up, left, diag, dcur, validExpr, rnew)                    \
    {                                                                          \
        const float m1_ = fminf(up, left);                                     \
        const float M1_ = fmaxf(up, left);                                     \
        const float mm_ = fminf(m1_, diag);                                    \
        const float xx_ = fmaxf(m1_, diag);                                    \
        const float mk_ = mm_ * KK;                                            \
        const float e1_ = ex2f(fmaf(-KK, xx_, mk_));                           \
        const float e2_ = ex2f(fmaf(-KK, M1_, mk_));                           \
        const float sm_ = fmaf(-GL2, lg2f(1.0f + e1_ + e2_), mm_);             \
        rnew = (validExpr) ? (dcur + sm_) : INFV;                              \
    }

// D = dot16(A'_row, xb[k]) via 8 packed f32x2 FMAs + horizontal add
#define PROD_D(bp, Aa, Ab, Ac, Ad, dOut)                                       \
    {                                                                          \
        const ulonglong2 Ba_ = (bp)[0];                                        \
        const ulonglong2 Bb_ = (bp)[1];                                        \
        const ulonglong2 Bc_ = (bp)[2];                                        \
        const ulonglong2 Bd_ = (bp)[3];                                        \
        u64 acc_ = fmul2(Aa.x, Ba_.x);                                         \
        acc_ = ffma2(Aa.y, Ba_.y, acc_);                                       \
        acc_ = ffma2(Ab.x, Bb_.x, acc_);                                       \
        acc_ = ffma2(Ab.y, Bb_.y, acc_);                                       \
        acc_ = ffma2(Ac.x, Bc_.x, acc_);                                       \
        acc_ = ffma2(Ac.y, Bc_.y, acc_);                                       \
        acc_ = ffma2(Ad.x, Bd_.x, acc_);                                       \
        acc_ = ffma2(Ad.y, Bd_.y, acc_);                                       \
        dOut = pairsum(acc_);                                                  \
    }

// One 32-row strip of the DP. S is a compile-time constant (0 or 1).
template <int S>
__device__ __forceinline__ float dp_strip(
    int L, int Lq, int a,
    const float* __restrict__ s_xb,   // this warp's xb tile (B-padded)
    float* __restrict__ s_ring,       // this warp's 32x32 D ring
    float* __restrict__ s_rowbuf)     // this warp's boundary row
{
    const float INFV = 1e10f;
    const float KK   = 14.4269504088896341f;   // log2(e)/gamma, gamma = 0.1
    const float GL2  = 0.069314718055994531f;  // gamma * ln(2)

    const int row = S * 32 + L;
    const ulonglong2* ap = (const ulonglong2*)&g_xpadA[((size_t)a * TLEN + row) * 16];
    const ulonglong2 Aa = ap[0], Ab = ap[1], Ac = ap[2], Ad = ap[3];

    float r1 = INFV;
    // diag carry: holds previous step's (post-override) up. First use at k=0
    // is cell (row, -L): only lane 0 / strip 0 needs corner R(-1,-1)=0 there.
    float dg = (S == 0 && L == 0) ? 0.0f : INFV;

    // ---------------- Phase A: k = 0..63 (produce D column + consume) -------
#pragma unroll 4
    for (int k = 0; k < TLEN; ++k) {
        // produce D[row][k]
        float dnew;
        {
            const ulonglong2* bp = (const ulonglong2*)&s_xb[k * 16];
            PROD_D(bp, Aa, Ab, Ac, Ad, dnew);
            s_ring[(k & 31) * 32 + L] = dnew;   // bank = L, conflict-free
        }

        // consume cell (row, j = k-L). Lane 0 reads a one-back slot (Lq=1)
        // and takes dnew from register: no same-step same-address LDS
        // (B300 smem has no store-forwarding).
        const float dld = s_ring[((k - Lq) & 31) * 32 + L];
        const float dcur = (L == 0) ? dnew : dld;
        float up = __shfl_up_sync(0xffffffffu, r1, 1);
        if (L == 0) up = (S == 0) ? INFV : s_rowbuf[k];   // R[31][j], j==k
        const float left = r1;

        float rnew;
        SOFTMIN_CELL(up, left, dg, dcur, k >= L, rnew);
        if (S == 0 && L == 31 && k >= L) s_rowbuf[k - L] = rnew;
        dg = up;       // diag for next step
        r1 = rnew;
    }

    // ---------------- Phase B: k = 64..94 (drain; j = k-L in [33,63]) -------
    // Lane 0 is invalid throughout phase B; no up override needed — its
    // results are discarded by the validity SEL and feed nothing live.
#pragma unroll 4
    for (int k = TLEN; k < TLEN + 31; ++k) {
        const float dcur = s_ring[((k - Lq) & 31) * 32 + L];
        const float up = __shfl_up_sync(0xffffffffu, r1, 1);
        const float left = r1;

        float rnew;
        SOFTMIN_CELL(up, left, dg, dcur, k < L + TLEN, rnew);
        if (S == 0 && L == 31) s_rowbuf[k - 31] = rnew;   // j in [33,63]
        dg = up;
        r1 = rnew;
    }
    return r1;
}

__global__ void __launch_bounds__(WPB * 32, 12) pairs_kernel() {
    __shared__ __align__(16) float s_xb[WPB][TLEN * 16];  // 8 KB: xb frames (B-padded)
    __shared__ float s_ring[WPB][32 * 32];                // 8 KB: D-column ring
    __shared__ float s_rowbuf[WPB][TLEN];                 // .5 KB: strip boundary row

    const int w = threadIdx.x >> 5;
    const int L = threadIdx.x & 31;
    const int Lq = L + (L == 0);    // ring read delay (lane 0 biased one back)
    const int idx = blockIdx.x * WPB + w;
    if (idx >= NPAIRS) return;

    // --- decode triangular pair index: off(a) = a*(255-a)/2 ---
    int a = (int)((255.0f - sqrtf(fmaxf(0.f, 65025.0f - 8.0f * (float)idx))) * 0.5f);
    if (a < 0) a = 0;
    if (a > 126) a = 126;
    while (a > 0 && (a * (255 - a)) / 2 > idx) --a;
    while (((a + 1) * (254 - a)) / 2 <= idx) ++a;
    const int b = a + 1 + (idx - (a * (255 - a)) / 2);

    // --- stage xb (64 frames x 16 floats, B padding) into shared ---
    {
        const float4* src4 = (const float4*)&g_xpadB[(size_t)b * TLEN * 16];
        float4* dst4 = (float4*)&s_xb[w][0];
#pragma unroll
        for (int t = L; t < TLEN * 4; t += 32) dst4[t] = src4[t];
    }
    __syncwarp();

    dp_strip<0>(L, Lq, a, s_xb[w], s_ring[w], s_rowbuf[w]);
    __syncwarp();   // strip 0's rowbuf writes -> strip 1's lane-0 reads
    const float Rv = dp_strip<1>(L, Lq, a, s_xb[w], s_ring[w], s_rowbuf[w]);

    if (L == 31) {
        g_R[a * NSEQ + b] = Rv;         // R[63][63]
        g_R[b * NSEQ + a] = Rv;         // sim is symmetric
    }
}

// ---------------------------------------------------------------------------
// Kernel 3: fused contrastive loss (one block, 32 warps). Warp w handles rows
// {w, w+32, w+64, w+96}: per-row lse - pos via deterministic butterfly
// reductions; then warp 0 sums the 128 partials. One graph node instead of
// two (per-node overhead measured ~4.5us on a trivial kernel).
// sim = R/ENERGY with zero diagonal.
// ---------------------------------------------------------------------------
__global__ void __launch_bounds__(1024) loss_kernel(float* __restrict__ out) {
    __shared__ float s_partial[NSEQ];
    const int wid  = threadIdx.x >> 5;        // 0..31
    const int lane = threadIdx.x & 31;
    const float INV_E = 2.0f;                 // 1/ENERGY
    const float L2E   = 1.4426950408889634f;  // log2(e)
    const float LN2   = 0.6931471805599453f;

#pragma unroll
    for (int q = 0; q < 4; ++q) {
        const int r = wid + q * 32;           // row 0..127

        float v[4];
#pragma unroll
        for (int p = 0; p < 4; ++p) {
            const int c = p * 32 + lane;
            v[p] = (c == r) ? 0.0f : g_R[r * NSEQ + c] * INV_E;
        }

        float mx = fmaxf(fmaxf(v[0], v[1]), fmaxf(v[2], v[3]));
#pragma unroll
        for (int o = 16; o > 0; o >>= 1)
            mx = fmaxf(mx, __shfl_xor_sync(0xffffffffu, mx, o));

        float sum = 0.f;
#pragma unroll
        for (int p = 0; p < 4; ++p)
            sum += ex2f((v[p] - mx) * L2E);
#pragma unroll
        for (int o = 16; o > 0; o >>= 1)
            sum += __shfl_xor_sync(0xffffffffu, sum, o);

        if (lane == 0) {
            const float lse = fmaf(LN2, lg2f(sum), mx);
            const float pos = g_R[r * NSEQ + ((r + 64) & 127)] * INV_E;
            s_partial[r] = lse - pos;
        }
    }
    __syncthreads();

    if (wid == 0) {
        float s = s_partial[lane] + s_partial[lane + 32]
                + s_partial[lane + 64] + s_partial[lane + 96];
#pragma unroll
        for (int o = 16; o > 0; o >>= 1)
            s += __shfl_xor_sync(0xffffffffu, s, o);
        if (lane == 0) out[0] = s * (1.0f / 128.0f);
    }
}

// ---------------------------------------------------------------------------
extern "C" void kernel_launch(void* const* d_in, const int* in_sizes, int n_in,
                              void* d_out, int out_size) {
    const float* xxx = (const float*)d_in[0];
    const float* yyy = (const float*)d_in[1];
    float* out = (float*)d_out;

    prep_kernel<<<(NSEQ * TLEN + 255) / 256, 256>>>(xxx, yyy);
    pairs_kernel<<<NPAIRS / WPB, WPB * 32>>>();
    loss_kernel<<<1, 1024>>>(out);
}